// round 3
// baseline (speedup 1.0000x reference)
#include <cuda_runtime.h>
#include <math.h>

#define BATCH   2
#define SEQ     2048
#define DMODEL  1024
#define NHEADS  16
#define HDIM    64
#define ROWS    (BATCH * SEQ)      /* 4096 */
#define QKVN    (3 * DMODEL)       /* 3072 */
#define PADW    68                 /* padded smem row stride (floats) for attention tiles */

/* ------------------------------------------------------------------ */
/* Scratch (device globals: no runtime allocation allowed)            */
/* ------------------------------------------------------------------ */
__device__ float g_qkv[(size_t)ROWS * QKVN];     /* [4096, 3072]  Q|K|V after proj (+RoPE in place) */
__device__ float g_ctx[(size_t)ROWS * DMODEL];   /* [4096, 1024]  attention context, (b,s,h,d)      */
__device__ float g_cos[SEQ * (HDIM / 2)];
__device__ float g_sin[SEQ * (HDIM / 2)];

/* ------------------------------------------------------------------ */
/* SGEMM: C[M,N] = A[M,K] @ B[K,N] + bias[N]                           */
/* 128x128 block tile, BK=8, 256 threads, 8x8 per-thread register tile */
/* ------------------------------------------------------------------ */
__global__ __launch_bounds__(256) void sgemm_bias_kernel(
    const float* __restrict__ A, const float* __restrict__ Bm,
    const float* __restrict__ bias, float* __restrict__ C,
    int M, int N, int K)
{
    __shared__ float As[8 * 132];   /* As[k][m], transposed A tile */
    __shared__ float Bs[8 * 132];   /* Bs[k][n]                    */

    const int tid = threadIdx.x;
    const int tx  = tid & 15;       /* 0..15 column group */
    const int ty  = tid >> 4;       /* 0..15 row group    */
    const int m0  = blockIdx.y * 128;
    const int n0  = blockIdx.x * 128;

    /* gmem staging pointers */
    const int ar   = tid >> 1;          /* A tile row 0..127   */
    const int aseg = (tid & 1) * 4;     /* A tile k segment    */
    const int brow = tid >> 5;          /* B tile row 0..7     */
    const int bcol = (tid & 31) * 4;    /* B tile col          */

    const float* Aptr = A  + (size_t)(m0 + ar) * K + aseg;
    const float* Bptr = Bm + (size_t)brow * N + n0 + bcol;

    float4 pa = *(const float4*)Aptr;
    float4 pb = *(const float4*)Bptr;

    float acc[8][8];
#pragma unroll
    for (int i = 0; i < 8; i++)
#pragma unroll
        for (int j = 0; j < 8; j++) acc[i][j] = 0.0f;

    const int kb_count = K >> 3;
    for (int kb = 0; kb < kb_count; kb++) {
        As[(aseg + 0) * 132 + ar] = pa.x;
        As[(aseg + 1) * 132 + ar] = pa.y;
        As[(aseg + 2) * 132 + ar] = pa.z;
        As[(aseg + 3) * 132 + ar] = pa.w;
        *(float4*)&Bs[brow * 132 + bcol] = pb;
        __syncthreads();

        if (kb + 1 < kb_count) {
            pa = *(const float4*)(Aptr + (size_t)(kb + 1) * 8);
            pb = *(const float4*)(Bptr + (size_t)(kb + 1) * 8 * N);
        }

#pragma unroll
        for (int kk = 0; kk < 8; kk++) {
            float a[8], b[8];
            *(float4*)&a[0] = *(const float4*)&As[kk * 132 + ty * 4];
            *(float4*)&a[4] = *(const float4*)&As[kk * 132 + 64 + ty * 4];
            *(float4*)&b[0] = *(const float4*)&Bs[kk * 132 + tx * 4];
            *(float4*)&b[4] = *(const float4*)&Bs[kk * 132 + 64 + tx * 4];
#pragma unroll
            for (int i = 0; i < 8; i++)
#pragma unroll
                for (int j = 0; j < 8; j++)
                    acc[i][j] = fmaf(a[i], b[j], acc[i][j]);
        }
        __syncthreads();
    }

    /* epilogue: + bias, store */
#pragma unroll
    for (int i = 0; i < 8; i++) {
        const int m = m0 + ((i < 4) ? (ty * 4 + i) : (64 + ty * 4 + i - 4));
#pragma unroll
        for (int jh = 0; jh < 2; jh++) {
            const int n = n0 + jh * 64 + tx * 4;
            float4 r;
            r.x = acc[i][jh * 4 + 0] + bias[n + 0];
            r.y = acc[i][jh * 4 + 1] + bias[n + 1];
            r.z = acc[i][jh * 4 + 2] + bias[n + 2];
            r.w = acc[i][jh * 4 + 3] + bias[n + 3];
            *(float4*)&C[(size_t)m * N + n] = r;
        }
    }
}

/* ------------------------------------------------------------------ */
/* RoPE cos/sin table (fp64 sincos: safe range reduction for args up   */
/* to ~2048; argument itself computed in fp32 to match the reference). */
/* ------------------------------------------------------------------ */
__global__ void rope_table_kernel()
{
    const int i = blockIdx.x * blockDim.x + threadIdx.x;   /* SEQ*32 = 65536 */
    const int j = i & 31;
    const int s = i >> 5;
    const float expo = (float)(2 * j) * (1.0f / (float)HDIM);
    const float invf = powf(10000.0f, -expo);
    const float freq = (float)s * invf;    /* fp32 product, matches jnp */
    double sd, cd;
    sincos((double)freq, &sd, &cd);
    g_cos[i] = (float)cd;
    g_sin[i] = (float)sd;
}

/* ------------------------------------------------------------------ */
/* In-place RoPE on the Q and K portions of g_qkv.                     */
/* One thread per (b, s, h, j<32) rotation pair; handles Q and K.      */
/* ------------------------------------------------------------------ */
__global__ void rope_apply_kernel()
{
    const int i = blockIdx.x * blockDim.x + threadIdx.x;   /* 2*2048*16*32 = 2^21 */
    const int j = i & 31;
    const int h = (i >> 5) & (NHEADS - 1);
    const int s = (i >> 9) & (SEQ - 1);
    const int b = i >> 20;

    const float c  = g_cos[s * 32 + j];
    const float sn = g_sin[s * 32 + j];
    const size_t base = ((size_t)(b * SEQ + s)) * QKVN + h * HDIM;

    float q1 = g_qkv[base + j];
    float q2 = g_qkv[base + j + 32];
    g_qkv[base + j]      = q1 * c - q2 * sn;
    g_qkv[base + j + 32] = q2 * c + q1 * sn;

    float k1 = g_qkv[base + DMODEL + j];
    float k2 = g_qkv[base + DMODEL + j + 32];
    g_qkv[base + DMODEL + j]      = k1 * c - k2 * sn;
    g_qkv[base + DMODEL + j + 32] = k2 * c + k1 * sn;
}

/* ------------------------------------------------------------------ */
/* Flash attention, fp32, causal. Br=Bc=64, 256 threads.               */
/* Thread (tx=t&15, ty=t>>4) owns rows {ty*4+i} and cols {tx+16*j}.    */
/* grid = (32 query blocks [reversed for load balance], 32 bh pairs)   */
/* ------------------------------------------------------------------ */
__global__ __launch_bounds__(256) void attn_kernel()
{
    extern __shared__ float sm[];
    float* Qs = sm;
    float* Ks = sm + 64 * PADW;
    float* Vs = sm + 2 * 64 * PADW;
    float* Ss = sm + 3 * 64 * PADW;

    const int tid = threadIdx.x;
    const int bh  = blockIdx.y;
    const int b   = bh >> 4;
    const int h   = bh & (NHEADS - 1);
    const int qi  = (int)(gridDim.x - 1) - (int)blockIdx.x;  /* heavy blocks first */
    const int q0  = qi * 64;

    const float* base = g_qkv + (size_t)b * SEQ * QKVN + h * HDIM;

    /* load Q tile */
    for (int idx = tid; idx < 64 * 16; idx += 256) {
        const int r  = idx >> 4;
        const int d4 = (idx & 15) * 4;
        float4 v = *(const float4*)(base + (size_t)(q0 + r) * QKVN + d4);
        Qs[r * PADW + d4 + 0] = v.x;
        Qs[r * PADW + d4 + 1] = v.y;
        Qs[r * PADW + d4 + 2] = v.z;
        Qs[r * PADW + d4 + 3] = v.w;
    }

    const int tx = tid & 15;
    const int ty = tid >> 4;

    float mi[4], li[4], acc[4][4];
#pragma unroll
    for (int i = 0; i < 4; i++) {
        mi[i] = -1e30f;
        li[i] = 0.0f;
#pragma unroll
        for (int j = 0; j < 4; j++) acc[i][j] = 0.0f;
    }

    for (int kt = 0; kt <= qi; kt++) {
        __syncthreads();   /* previous PV / score reads done before overwrite */
        const int k0 = kt * 64;

        /* load K and V tiles */
        for (int idx = tid; idx < 64 * 16; idx += 256) {
            const int r  = idx >> 4;
            const int d4 = (idx & 15) * 4;
            const float* rp = base + (size_t)(k0 + r) * QKVN + d4;
            float4 kv = *(const float4*)(rp + DMODEL);
            float4 vv = *(const float4*)(rp + 2 * DMODEL);
            Ks[r * PADW + d4 + 0] = kv.x;
            Ks[r * PADW + d4 + 1] = kv.y;
            Ks[r * PADW + d4 + 2] = kv.z;
            Ks[r * PADW + d4 + 3] = kv.w;
            Vs[r * PADW + d4 + 0] = vv.x;
            Vs[r * PADW + d4 + 1] = vv.y;
            Vs[r * PADW + d4 + 2] = vv.z;
            Vs[r * PADW + d4 + 3] = vv.w;
        }
        __syncthreads();

        /* scores: s = Q K^T (4x4 per thread) */
        float s[4][4];
#pragma unroll
        for (int i = 0; i < 4; i++)
#pragma unroll
            for (int j = 0; j < 4; j++) s[i][j] = 0.0f;

#pragma unroll
        for (int kk = 0; kk < 64; kk += 4) {
            float4 qa[4], kb[4];
#pragma unroll
            for (int i = 0; i < 4; i++)
                qa[i] = *(const float4*)&Qs[(ty * 4 + i) * PADW + kk];
#pragma unroll
            for (int j = 0; j < 4; j++)
                kb[j] = *(const float4*)&Ks[(tx + 16 * j) * PADW + kk];
#pragma unroll
            for (int i = 0; i < 4; i++)
#pragma unroll
                for (int j = 0; j < 4; j++) {
                    s[i][j] = fmaf(qa[i].x, kb[j].x, s[i][j]);
                    s[i][j] = fmaf(qa[i].y, kb[j].y, s[i][j]);
                    s[i][j] = fmaf(qa[i].z, kb[j].z, s[i][j]);
                    s[i][j] = fmaf(qa[i].w, kb[j].w, s[i][j]);
                }
        }

        const bool diag = (kt == qi);

        /* online softmax per row */
#pragma unroll
        for (int i = 0; i < 4; i++) {
            const int qg = q0 + ty * 4 + i;
            float rmax = -1e30f;
#pragma unroll
            for (int j = 0; j < 4; j++) {
                s[i][j] *= 0.125f;    /* 1/sqrt(64) */
                if (diag && (k0 + tx + 16 * j) > qg) s[i][j] = -1e30f;
                rmax = fmaxf(rmax, s[i][j]);
            }
            rmax = fmaxf(rmax, __shfl_xor_sync(0xffffffffu, rmax, 1));
            rmax = fmaxf(rmax, __shfl_xor_sync(0xffffffffu, rmax, 2));
            rmax = fmaxf(rmax, __shfl_xor_sync(0xffffffffu, rmax, 4));
            rmax = fmaxf(rmax, __shfl_xor_sync(0xffffffffu, rmax, 8));

            const float newm    = fmaxf(mi[i], rmax);
            const float rescale = __expf(mi[i] - newm);
            mi[i] = newm;

            float p[4];
            float psum = 0.0f;
#pragma unroll
            for (int j = 0; j < 4; j++) {
                p[j] = __expf(s[i][j] - newm);
                psum += p[j];
            }
            psum += __shfl_xor_sync(0xffffffffu, psum, 1);
            psum += __shfl_xor_sync(0xffffffffu, psum, 2);
            psum += __shfl_xor_sync(0xffffffffu, psum, 4);
            psum += __shfl_xor_sync(0xffffffffu, psum, 8);

            li[i] = li[i] * rescale + psum;
#pragma unroll
            for (int j = 0; j < 4; j++) {
                acc[i][j] *= rescale;
                Ss[(ty * 4 + i) * PADW + tx + 16 * j] = p[j];
            }
        }
        __syncthreads();

        /* O += P @ V */
#pragma unroll 4
        for (int kk = 0; kk < 64; kk++) {
            float pv[4], vv[4];
#pragma unroll
            for (int i = 0; i < 4; i++) pv[i] = Ss[(ty * 4 + i) * PADW + kk];
#pragma unroll
            for (int j = 0; j < 4; j++) vv[j] = Vs[kk * PADW + tx + 16 * j];
#pragma unroll
            for (int i = 0; i < 4; i++)
#pragma unroll
                for (int j = 0; j < 4; j++)
                    acc[i][j] = fmaf(pv[i], vv[j], acc[i][j]);
        }
    }

    /* normalize + write context in (b, s, h, d) layout */
#pragma unroll
    for (int i = 0; i < 4; i++) {
        const float inv = 1.0f / li[i];
        const int srow  = q0 + ty * 4 + i;
        const size_t o  = ((size_t)(b * SEQ + srow) * NHEADS + h) * HDIM;
#pragma unroll
        for (int j = 0; j < 4; j++)
            g_ctx[o + tx + 16 * j] = acc[i][j] * inv;
    }
}

/* ------------------------------------------------------------------ */
/* Launch                                                              */
/* ------------------------------------------------------------------ */
extern "C" void kernel_launch(void* const* d_in, const int* in_sizes, int n_in,
                              void* d_out, int out_size)
{
    const float* x     = (const float*)d_in[0];   /* [2, 2048, 1024] */
    const float* W_qkv = (const float*)d_in[1];   /* [1024, 3072]    */
    const float* b_qkv = (const float*)d_in[2];   /* [3072]          */
    const float* W_out = (const float*)d_in[3];   /* [1024, 1024]    */
    const float* b_out = (const float*)d_in[4];   /* [1024]          */
    float* out = (float*)d_out;                   /* [2, 2048, 1024] */

    void* p_qkv = nullptr;
    void* p_ctx = nullptr;
    cudaGetSymbolAddress(&p_qkv, g_qkv);
    cudaGetSymbolAddress(&p_ctx, g_ctx);

    /* RoPE table (independent; launched first) */
    rope_table_kernel<<<(SEQ * 32) / 256, 256>>>();

    /* QKV projection + bias */
    sgemm_bias_kernel<<<dim3(QKVN / 128, ROWS / 128), 256>>>(
        x, W_qkv, b_qkv, (float*)p_qkv, ROWS, QKVN, DMODEL);

    /* RoPE in place on Q and K */
    rope_apply_kernel<<<(BATCH * SEQ * NHEADS * 32) / 256, 256>>>();

    /* Flash attention */
    const int attn_smem = 4 * 64 * PADW * (int)sizeof(float);  /* 69632 B */
    cudaFuncSetAttribute(attn_kernel,
                         cudaFuncAttributeMaxDynamicSharedMemorySize, attn_smem);
    attn_kernel<<<dim3(SEQ / 64, BATCH * NHEADS), 256, attn_smem>>>();

    /* Output projection + bias */
    sgemm_bias_kernel<<<dim3(DMODEL / 128, ROWS / 128), 256>>>(
        (const float*)p_ctx, W_out, b_out, out, ROWS, DMODEL, DMODEL);
}